// round 15
// baseline (speedup 1.0000x reference)
#include <cuda_runtime.h>
#include <cuda_bf16.h>
#include <cstdint>

// OHEM smooth-L1 loss. y_pred,y_true: [64, 262144] fp32 -> scalar fp32.
// memset + ONE fused kernel:
//  sweep  : 8192 elem/block, 2 front-batched chunks (__ldcs); stage
//           "interesting" (p,t) pairs (pos OR |p|>=1.5625) in private smem
//           slots; pos stats + 2048-bin SMEM hist + big-neg a-sum; coalesced
//           nonzero-bin flush to global REDs.
//  ticket : __syncthreads + ONE release-fence+atomic per block (CUB-lookback
//           pattern). Last block of each row runs the row-finish on the
//           L2-HOT histogram (warp-0 select + linear reconstruction).
//  final  : global ticket -> single-warp final scalar.

static constexpr int B = 64;
static constexpr int N = 256 * 256 * 4;        // 262144
static constexpr int NBINS = 2048;
static constexpr int SHIFT = 13;               // (key-CUT)>>13 -> 2048 bins
static constexpr unsigned CUT_BITS = 0x3FC80000u;   // 1.5625f
static constexpr float   CUTF = 1.5625f;

static constexpr int TPB = 256;
static constexpr int VEC = 4;
static constexpr int ITERS = 4;                 // per chunk
static constexpr int CHUNKS = 2;
static constexpr int EPB = TPB * VEC * ITERS * CHUNKS;   // 8192
static constexpr int BPR = N / EPB;             // 32

struct Zeroed {
    unsigned hist[B][NBINS];
    unsigned pos_cnt[B];
    unsigned big_cnt[B];
    double   pos_sum[B];
    double   big_suma[B];
    double   ns, nc;
    unsigned row_ticket[B];
    unsigned ticket2;
};
__device__ Zeroed g_z;         // ~513 KB memset per launch

__device__ __forceinline__ float fsl1(float a) {
    float u = fminf(a, 1.0f);
    return fmaf(u, fmaf(0.5f, u, -1.0f), a);   // exact smooth_l1, branch-free
}
__device__ __forceinline__ float bin_center(int b) {
    return __uint_as_float(CUT_BITS + ((unsigned)b << SHIFT) + (1u << (SHIFT - 1)));
}

// Warp-local suffix select over a 2048-bin hist via loader functor.
// All 32 lanes active. Returns in every lane: b*, c = count(bins > b*),
// with c < keff <= c + h[b*].
template <typename LoadFn>
__device__ void warp_select_g(LoadFn ld, unsigned keff, int& ob, unsigned& oc) {
    const int lane = threadIdx.x & 31;
    const int chunk = NBINS >> 5;              // 64
    unsigned cs = 0;
    #pragma unroll
    for (int j = 0; j < chunk; j++) cs += ld(lane * chunk + j);
    unsigned v = cs;
    #pragma unroll
    for (int off = 1; off < 32; off <<= 1) {
        unsigned g = __shfl_down_sync(0xffffffffu, v, off);
        if (lane + off < 32) v += g;
    }
    unsigned vnext = __shfl_down_sync(0xffffffffu, v, 1);
    if (lane == 31) vnext = 0u;
    bool hit = (v >= keff) && (vnext < keff);
    unsigned hb = __ballot_sync(0xffffffffu, hit);
    int c = __ffs(hb) - 1;
    unsigned S = __shfl_sync(0xffffffffu, vnext, c);
    ob = 0; oc = 0;
    #pragma unroll
    for (int g = (chunk >> 5) - 1; g >= 0; g--) {
        unsigned hv = ld(c * chunk + g * 32 + lane);
        unsigned w = hv;
        #pragma unroll
        for (int off = 1; off < 32; off <<= 1) {
            unsigned gg = __shfl_down_sync(0xffffffffu, w, off);
            if (lane + off < 32) w += gg;
        }
        unsigned wnext = __shfl_down_sync(0xffffffffu, w, 1);
        if (lane == 31) wnext = 0u;
        unsigned tot = __shfl_sync(0xffffffffu, w, 0);
        bool hit2 = (S + w >= keff) && (S + wnext < keff);
        unsigned hb2 = __ballot_sync(0xffffffffu, hit2);
        if (hb2) {
            int l = __ffs(hb2) - 1;
            unsigned wl = __shfl_sync(0xffffffffu, w, l);
            unsigned hl = __shfl_sync(0xffffffffu, hv, l);
            ob = c * chunk + g * 32 + l;
            oc = S + wl - hl;
            return;
        }
        S += tot;
    }
}

// ---------------- fused kernel -----------------------------------------------
__global__ void __launch_bounds__(TPB, 4) fused(const float* __restrict__ yp,
                                                const float* __restrict__ yt,
                                                float* __restrict__ out) {
    __shared__ float2 sbuf[TPB][17];            // 16 slots + pad; 34.8 KB
    __shared__ unsigned s_hist[NBINS];          // 8 KB block-local histogram
    __shared__ float rs_ps[8], rs_bs[8];
    __shared__ int   rs_pc[8], rs_bc[8];
    __shared__ int sh_fin, sh_last, sh_fb;
    __shared__ double sh_negr, sh_kd;
    __shared__ int s_b; __shared__ unsigned s_c;
    const int r = blockIdx.y;
    const int tid = threadIdx.x;
    const int lane = tid & 31;
    const int w = tid >> 5;
    const size_t base0 = (size_t)r * N + (size_t)blockIdx.x * EPB;

    #pragma unroll
    for (int i = tid; i < NBINS; i += TPB) s_hist[i] = 0u;
    __syncthreads();

    float psum = 0.f, bsum = 0.f; int pc = 0, bc = 0;

    #pragma unroll
    for (int ch = 0; ch < CHUNKS; ch++) {
        const size_t base = base0 + (size_t)ch * (TPB * VEC * ITERS);

        // front-batch 8 x LDG.128 (streaming / evict-first)
        float4 P[ITERS], T[ITERS];
        #pragma unroll
        for (int it = 0; it < ITERS; it++) {
            size_t idx = base + (size_t)it * (TPB * VEC) + (size_t)tid * VEC;
            P[it] = __ldcs(reinterpret_cast<const float4*>(yp + idx));
            T[it] = __ldcs(reinterpret_cast<const float4*>(yt + idx));
        }

        // filter + stage (1 FFMA + 1 FSETP + predicated STS.64 per elem)
        int cnt = 0;
        #pragma unroll
        for (int it = 0; it < ITERS; it++) {
            float pv[4] = {P[it].x, P[it].y, P[it].z, P[it].w};
            float tv[4] = {T[it].x, T[it].y, T[it].z, T[it].w};
            #pragma unroll
            for (int j = 0; j < 4; j++) {
                // t!=0 -> w huge; t==0 -> w=|p|.  interesting <=> w >= CUTF
                float wv = fmaf(fabsf(tv[j]), 1e38f, fabsf(pv[j]));
                if (wv >= CUTF) { sbuf[tid][cnt] = make_float2(pv[j], tv[j]); cnt++; }
            }
        }

        // process staged entries -> smem hist (fast atomics) + scalars
        for (int c = 0; c < cnt; c++) {
            float2 e = sbuf[tid][c];
            if (e.y != 0.f) {                    // positive
                psum += fsl1(fabsf(e.x - e.y));
                pc++;
            } else {                             // big negative (|p| >= 1.5625)
                float a = fabsf(e.x);
                unsigned bin = (__float_as_uint(a) - CUT_BITS) >> SHIFT;
                bin = min(bin, (unsigned)(NBINS - 1));
                atomicAdd(&s_hist[bin], 1u);
                bsum += a; bc++;
            }
        }
    }

    // per-warp shuffle reduce of the 4 scalars
    #pragma unroll
    for (int o = 16; o; o >>= 1) {
        psum += __shfl_down_sync(0xffffffffu, psum, o);
        bsum += __shfl_down_sync(0xffffffffu, bsum, o);
        pc   += __shfl_down_sync(0xffffffffu, pc, o);
        bc   += __shfl_down_sync(0xffffffffu, bc, o);
    }
    if (lane == 0) { rs_ps[w] = psum; rs_bs[w] = bsum; rs_pc[w] = pc; rs_bc[w] = bc; }
    __syncthreads();

    // flush block hist: coalesced, only nonzero bins
    #pragma unroll
    for (int i = tid; i < NBINS; i += TPB) {
        unsigned h = s_hist[i];
        if (h) atomicAdd(&g_z.hist[r][i], h);
    }
    if (tid == 0) {
        double PS = 0.0, BS = 0.0; int PC = 0, BC = 0;
        #pragma unroll
        for (int i = 0; i < 8; i++) {
            PS += (double)rs_ps[i]; BS += (double)rs_bs[i];
            PC += rs_pc[i]; BC += rs_bc[i];
        }
        if (PC) { atomicAdd(&g_z.pos_sum[r], PS); atomicAdd(&g_z.pos_cnt[r], (unsigned)PC); }
        if (BC) { atomicAdd(&g_z.big_suma[r], BS); atomicAdd(&g_z.big_cnt[r], (unsigned)BC); }
    }

    // ---- row ticket: barrier + ONE release-fence+atomic (CUB pattern) ----
    __syncthreads();                             // intra-block HB for all REDs
    if (tid == 0) {
        __threadfence();                         // release this block's work
        unsigned old = atomicAdd(&g_z.row_ticket[r], 1u);
        sh_fin = 0;
        if (old == (unsigned)(BPR - 1)) { __threadfence(); sh_fin = 1; }  // acquire
    }
    __syncthreads();
    if (!sh_fin) return;

    // ================= row finish (hist is L2-hot) ===========================
    const unsigned pcr = g_z.pos_cnt[r];
    const unsigned bcr = g_z.big_cnt[r];
    unsigned k = 2u * pcr; if (k > (unsigned)(N - 1)) k = (unsigned)(N - 1);

    if (w == 0) {
        const double bsa = g_z.big_suma[r];
        const unsigned keff = (k < bcr) ? k : bcr;
        const unsigned* __restrict__ h = g_z.hist[r];
        double negr = 0.0;
        if (keff > 0) {
            int b1; unsigned cab;
            warp_select_g([h](int i) { return h[i]; }, keff, b1, cab);
            double acc = 0.0;                   // a-sum over unselected bigs
            for (int b = lane; b < b1; b += 32)
                acc += (double)h[b] * (double)bin_center(b);
            #pragma unroll
            for (int o = 16; o; o >>= 1) acc += __shfl_down_sync(0xffffffffu, acc, o);
            if (lane == 0) {
                unsigned part_unsel = h[b1] - (keff - cab);
                acc += (double)part_unsel * (double)bin_center(b1);
                negr = bsa - acc - 0.5 * (double)keff;
            }
        }
        if (lane == 0) { sh_negr = negr; sh_kd = (double)k; sh_fb = (bcr < k); }
    }
    __syncthreads();

    // rare fallback (never taken for this distribution): block-wide, reuse sbuf
    if (sh_fb) {
        unsigned* f_h = reinterpret_cast<unsigned*>(&sbuf[0][0]);
        float*    f_f = reinterpret_cast<float*>(&sbuf[0][0]) + NBINS;
        for (int i = tid; i < NBINS; i += TPB) { f_h[i] = 0u; f_f[i] = 0.f; }
        __syncthreads();
        const size_t rb = (size_t)r * N;
        for (int i = tid; i < N; i += TPB) {
            float p = yp[rb + i], t = yt[rb + i];
            if (t == 0.f) {
                float a = fabsf(p);
                if (a < CUTF) {
                    unsigned bin = __float_as_uint(a) >> 21;
                    bin = min(bin, (unsigned)(NBINS - 1));
                    atomicAdd(&f_h[bin], 1u);
                    atomicAdd(&f_f[bin], fsl1(a));
                }
            }
        }
        __syncthreads();
        unsigned tc = 0;
        for (int i = tid; i < NBINS; i += TPB) tc += f_h[i];
        #pragma unroll
        for (int o = 16; o; o >>= 1) tc += __shfl_down_sync(0xffffffffu, tc, o);
        if (lane == 0) rs_pc[w] = (int)tc;
        __syncthreads();
        unsigned tot = 0;
        for (int i = 0; i < 8; i++) tot += (unsigned)rs_pc[i];
        unsigned kc = k - bcr; if (kc > tot) kc = tot;
        if (kc > 0) {
            if (w == 0) {
                int b1; unsigned cab;
                warp_select_g([f_h](int i) { return f_h[i]; }, kc, b1, cab);
                if (lane == 0) { s_b = b1; s_c = cab; }
            }
            __syncthreads();
            const int b1 = s_b; const unsigned cab = s_c;
            double ext = 0.0;
            for (int b = b1 + 1 + tid; b < NBINS; b += TPB) ext += (double)f_f[b];
            #pragma unroll
            for (int o = 16; o; o >>= 1) ext += __shfl_down_sync(0xffffffffu, ext, o);
            if (lane == 0) rs_ps[w] = (float)ext;   // reuse; fallback precision ok
            __syncthreads();
            if (tid == 0) {
                double e = 0.0;
                for (int i = 0; i < 8; i++) e += (double)rs_ps[i];
                unsigned part = kc - cab;
                if (f_h[b1]) e += (double)part * ((double)f_f[b1] / (double)f_h[b1]);
                sh_negr += e;
            }
            __syncthreads();
        }
    }

    // ---- global ticket -> final scalar ----
    if (tid == 0) {
        atomicAdd(&g_z.ns, sh_negr);
        atomicAdd(&g_z.nc, sh_kd);
        __threadfence();
        unsigned old = atomicAdd(&g_z.ticket2, 1u);
        sh_last = 0;
        if (old == (unsigned)(B - 1)) { __threadfence(); sh_last = 1; }
    }
    __syncthreads();
    if (!sh_last) return;

    if (w == 0) {
        double ps  = g_z.pos_sum[lane] + g_z.pos_sum[lane + 32];
        double pcs = (double)g_z.pos_cnt[lane] + (double)g_z.pos_cnt[lane + 32];
        #pragma unroll
        for (int o = 16; o; o >>= 1) {
            ps  += __shfl_down_sync(0xffffffffu, ps, o);
            pcs += __shfl_down_sync(0xffffffffu, pcs, o);
        }
        if (lane == 0) {
            double NS = g_z.ns, NC = g_z.nc;
            double pos_loss = (pcs > 0.0) ? ps / pcs : 0.0;
            double neg_loss = (NC > 0.0) ? NS / NC : 0.0;
            out[0] = (float)(2.0 * pos_loss + neg_loss);
        }
    }
}

// ---------------- launch ------------------------------------------------------
extern "C" void kernel_launch(void* const* d_in, const int* in_sizes, int n_in,
                              void* d_out, int out_size) {
    const float* yp = (const float*)d_in[0];
    const float* yt = (const float*)d_in[1];
    float* out = (float*)d_out;

    void* zp = nullptr;
    cudaGetSymbolAddress(&zp, g_z);
    cudaMemsetAsync(zp, 0, sizeof(Zeroed));

    fused<<<dim3(BPR, B), TPB>>>(yp, yt, out);
}

// round 16
// speedup vs baseline: 1.0173x; 1.0173x over previous
#include <cuda_runtime.h>
#include <cuda_bf16.h>
#include <cstdint>

// OHEM smooth-L1 loss. y_pred,y_true: [64, 262144] fp32 -> scalar fp32.
//  memset : zero scratch (~513 KB).
//  pass_a : sweep, 16384 elem/block in 4 front-batched chunks (__ldcs);
//           stage "interesting" (p,t) pairs (pos OR |p|>=1.5625) in private
//           smem slots; pos stats + 2048-bin SMEM hist + big-neg a-sum;
//           single coalesced nonzero-bin flush to global REDs.
//  pass_e : 64 blocks x 128 thr, one block/row. Warp 0: uint4 hist loads
//           (MLP=16) + 4-way-ILP double sums -> top-k select + linear neg-sum
//           reconstruction. Rare exact fallback block-wide. 64-block ticket ->
//           single-warp final scalar.

static constexpr int B = 64;
static constexpr int N = 256 * 256 * 4;        // 262144
static constexpr int NBINS = 2048;
static constexpr int SHIFT = 13;               // (key-CUT)>>13 -> 2048 bins
static constexpr unsigned CUT_BITS = 0x3FC80000u;   // 1.5625f
static constexpr float   CUTF = 1.5625f;

static constexpr int TPB = 256;
static constexpr int VEC = 4;
static constexpr int ITERS = 4;                 // per chunk
static constexpr int CHUNKS = 4;
static constexpr int EPB = TPB * VEC * ITERS * CHUNKS;   // 16384
static constexpr int BPR = N / EPB;             // 16

static constexpr int TPE = 128;                 // pass_e block (4 warps)

struct __align__(16) Zeroed {
    unsigned hist[B][NBINS];
    unsigned pos_cnt[B];
    unsigned big_cnt[B];
    double   pos_sum[B];
    double   big_suma[B];
    double   ns, nc;
    unsigned ticket;
};
__device__ Zeroed g_z;         // ~513 KB memset per launch

__device__ __forceinline__ float fsl1(float a) {
    float u = fminf(a, 1.0f);
    return fmaf(u, fmaf(0.5f, u, -1.0f), a);   // exact smooth_l1, branch-free
}
__device__ __forceinline__ float bin_center(int b) {
    return __uint_as_float(CUT_BITS + ((unsigned)b << SHIFT) + (1u << (SHIFT - 1)));
}

// ---------------- Pass A: chunked sweep with smem hist aggregation -----------
__global__ void __launch_bounds__(TPB, 4) pass_a(const float* __restrict__ yp,
                                                 const float* __restrict__ yt) {
    __shared__ float2 sbuf[TPB][17];            // 16 slots + pad; 34.8 KB
    __shared__ unsigned s_hist[NBINS];          // 8 KB block-local histogram
    __shared__ float rs_ps[8], rs_bs[8];
    __shared__ int   rs_pc[8], rs_bc[8];
    const int r = blockIdx.y;
    const int tid = threadIdx.x;
    const unsigned lane = tid & 31u;
    const int w = tid >> 5;
    const size_t base0 = (size_t)r * N + (size_t)blockIdx.x * EPB;

    #pragma unroll
    for (int i = tid; i < NBINS; i += TPB) s_hist[i] = 0u;
    __syncthreads();

    float psum = 0.f, bsum = 0.f; int pc = 0, bc = 0;

    #pragma unroll
    for (int ch = 0; ch < CHUNKS; ch++) {
        const size_t base = base0 + (size_t)ch * (TPB * VEC * ITERS);

        // front-batch 8 x LDG.128 (streaming / evict-first)
        float4 P[ITERS], T[ITERS];
        #pragma unroll
        for (int it = 0; it < ITERS; it++) {
            size_t idx = base + (size_t)it * (TPB * VEC) + (size_t)tid * VEC;
            P[it] = __ldcs(reinterpret_cast<const float4*>(yp + idx));
            T[it] = __ldcs(reinterpret_cast<const float4*>(yt + idx));
        }

        // filter + stage (1 FFMA + 1 FSETP + predicated STS.64 per elem)
        int cnt = 0;
        #pragma unroll
        for (int it = 0; it < ITERS; it++) {
            float pv[4] = {P[it].x, P[it].y, P[it].z, P[it].w};
            float tv[4] = {T[it].x, T[it].y, T[it].z, T[it].w};
            #pragma unroll
            for (int j = 0; j < 4; j++) {
                // t!=0 -> w huge; t==0 -> w=|p|.  interesting <=> w >= CUTF
                float wv = fmaf(fabsf(tv[j]), 1e38f, fabsf(pv[j]));
                if (wv >= CUTF) { sbuf[tid][cnt] = make_float2(pv[j], tv[j]); cnt++; }
            }
        }

        // process staged entries -> smem hist (fast atomics) + scalars
        for (int c = 0; c < cnt; c++) {
            float2 e = sbuf[tid][c];
            if (e.y != 0.f) {                    // positive
                psum += fsl1(fabsf(e.x - e.y));
                pc++;
            } else {                             // big negative (|p| >= 1.5625)
                float a = fabsf(e.x);
                unsigned bin = (__float_as_uint(a) - CUT_BITS) >> SHIFT;
                bin = min(bin, (unsigned)(NBINS - 1));
                atomicAdd(&s_hist[bin], 1u);
                bsum += a; bc++;
            }
        }
    }

    // per-warp shuffle reduce of the 4 scalars
    #pragma unroll
    for (int o = 16; o; o >>= 1) {
        psum += __shfl_down_sync(0xffffffffu, psum, o);
        bsum += __shfl_down_sync(0xffffffffu, bsum, o);
        pc   += __shfl_down_sync(0xffffffffu, pc, o);
        bc   += __shfl_down_sync(0xffffffffu, bc, o);
    }
    if (lane == 0) { rs_ps[w] = psum; rs_bs[w] = bsum; rs_pc[w] = pc; rs_bc[w] = bc; }
    __syncthreads();

    // flush block hist: coalesced, only nonzero bins
    #pragma unroll
    for (int i = tid; i < NBINS; i += TPB) {
        unsigned h = s_hist[i];
        if (h) atomicAdd(&g_z.hist[r][i], h);
    }
    if (tid == 0) {
        double PS = 0.0, BS = 0.0; int PC = 0, BC = 0;
        #pragma unroll
        for (int i = 0; i < 8; i++) {
            PS += (double)rs_ps[i]; BS += (double)rs_bs[i];
            PC += rs_pc[i]; BC += rs_bc[i];
        }
        if (PC) { atomicAdd(&g_z.pos_sum[r], PS); atomicAdd(&g_z.pos_cnt[r], (unsigned)PC); }
        if (BC) { atomicAdd(&g_z.big_suma[r], BS); atomicAdd(&g_z.big_cnt[r], (unsigned)BC); }
    }
}

// Warp-local suffix select over a 2048-bin GLOBAL hist using uint4 loads.
// All 32 lanes active. Returns in every lane: b*, c = count(bins > b*),
// with c < keff <= c + h[b*].
__device__ void warp_select_u4(const unsigned* __restrict__ h, unsigned keff,
                               int& ob, unsigned& oc) {
    const int lane = threadIdx.x & 31;
    const uint4* __restrict__ h4 = reinterpret_cast<const uint4*>(h);
    // stage 1: lane owns bins [lane*64, lane*64+64) = 16 uint4 (MLP=16)
    unsigned s0 = 0, s1 = 0, s2 = 0, s3 = 0;
    #pragma unroll
    for (int j = 0; j < 16; j++) {
        uint4 v = __ldg(&h4[lane * 16 + j]);
        s0 += v.x; s1 += v.y; s2 += v.z; s3 += v.w;
    }
    unsigned v = s0 + s1 + s2 + s3;
    #pragma unroll
    for (int off = 1; off < 32; off <<= 1) {
        unsigned g = __shfl_down_sync(0xffffffffu, v, off);
        if (lane + off < 32) v += g;
    }
    unsigned vnext = __shfl_down_sync(0xffffffffu, v, 1);
    if (lane == 31) vnext = 0u;
    bool hit = (v >= keff) && (vnext < keff);
    unsigned hb = __ballot_sync(0xffffffffu, hit);
    int c = __ffs(hb) - 1;
    unsigned S = __shfl_sync(0xffffffffu, vnext, c);
    ob = 0; oc = 0;
    // stage 2: the 64 bins of chunk c, two descending 32-bin groups (L1-hot)
    #pragma unroll
    for (int g = 1; g >= 0; g--) {
        unsigned hv = __ldg(&h[c * 64 + g * 32 + lane]);
        unsigned w = hv;
        #pragma unroll
        for (int off = 1; off < 32; off <<= 1) {
            unsigned gg = __shfl_down_sync(0xffffffffu, w, off);
            if (lane + off < 32) w += gg;
        }
        unsigned wnext = __shfl_down_sync(0xffffffffu, w, 1);
        if (lane == 31) wnext = 0u;
        unsigned tot = __shfl_sync(0xffffffffu, w, 0);
        bool hit2 = (S + w >= keff) && (S + wnext < keff);
        unsigned hb2 = __ballot_sync(0xffffffffu, hit2);
        if (hb2) {
            int l = __ffs(hb2) - 1;
            unsigned wl = __shfl_sync(0xffffffffu, w, l);
            unsigned hl = __shfl_sync(0xffffffffu, hv, l);
            ob = c * 64 + g * 32 + l;
            oc = S + wl - hl;
            return;
        }
        S += tot;
    }
}

// Shared-memory variant (fallback path), scalar loads.
__device__ void warp_select_sh(const unsigned* h, unsigned keff,
                               int& ob, unsigned& oc) {
    const int lane = threadIdx.x & 31;
    unsigned cs = 0;
    #pragma unroll 8
    for (int j = 0; j < 64; j++) cs += h[lane * 64 + j];
    unsigned v = cs;
    #pragma unroll
    for (int off = 1; off < 32; off <<= 1) {
        unsigned g = __shfl_down_sync(0xffffffffu, v, off);
        if (lane + off < 32) v += g;
    }
    unsigned vnext = __shfl_down_sync(0xffffffffu, v, 1);
    if (lane == 31) vnext = 0u;
    bool hit = (v >= keff) && (vnext < keff);
    unsigned hb = __ballot_sync(0xffffffffu, hit);
    int c = __ffs(hb) - 1;
    unsigned S = __shfl_sync(0xffffffffu, vnext, c);
    ob = 0; oc = 0;
    #pragma unroll
    for (int g = 1; g >= 0; g--) {
        unsigned hv = h[c * 64 + g * 32 + lane];
        unsigned w = hv;
        #pragma unroll
        for (int off = 1; off < 32; off <<= 1) {
            unsigned gg = __shfl_down_sync(0xffffffffu, w, off);
            if (lane + off < 32) w += gg;
        }
        unsigned wnext = __shfl_down_sync(0xffffffffu, w, 1);
        if (lane == 31) wnext = 0u;
        unsigned tot = __shfl_sync(0xffffffffu, w, 0);
        bool hit2 = (S + w >= keff) && (S + wnext < keff);
        unsigned hb2 = __ballot_sync(0xffffffffu, hit2);
        if (hb2) {
            int l = __ffs(hb2) - 1;
            unsigned wl = __shfl_sync(0xffffffffu, w, l);
            unsigned hl = __shfl_sync(0xffffffffu, hv, l);
            ob = c * 64 + g * 32 + l;
            oc = S + wl - hl;
            return;
        }
        S += tot;
    }
}

// ---------------- Pass E: one block/row, warp-0 ILP select -------------------
__global__ void __launch_bounds__(TPE) pass_e(const float* __restrict__ yp,
                                              const float* __restrict__ yt,
                                              float* __restrict__ out) {
    const int tid = threadIdx.x;
    const int lane = tid & 31, w = tid >> 5;
    const int r = blockIdx.x;
    __shared__ unsigned f_h[NBINS];             // fallback only
    __shared__ float    f_f[NBINS];             // fallback only
    __shared__ double sh_negr, sh_kd;
    __shared__ int sh_fb, sh_last;
    __shared__ int s_b; __shared__ unsigned s_c;

    const unsigned pcr = g_z.pos_cnt[r];
    const unsigned bcr = g_z.big_cnt[r];
    unsigned k = 2u * pcr; if (k > (unsigned)(N - 1)) k = (unsigned)(N - 1);

    if (w == 0) {
        const double bsa = g_z.big_suma[r];
        const unsigned keff = (k < bcr) ? k : bcr;
        const unsigned* __restrict__ h = g_z.hist[r];
        double negr = 0.0;
        if (keff > 0) {
            int b1; unsigned cab;
            warp_select_u4(h, keff, b1, cab);
            // a-sum over unselected bigs: uint4 loads (L1-hot), 4 indep accums
            const uint4* __restrict__ h4 = reinterpret_cast<const uint4*>(h);
            double a0 = 0.0, a1 = 0.0, a2 = 0.0, a3 = 0.0;
            for (int i4 = lane; i4 * 4 < b1; i4 += 32) {
                uint4 hv = __ldg(&h4[i4]);
                int b = i4 * 4;
                if (b + 0 < b1) a0 += (double)hv.x * (double)bin_center(b + 0);
                if (b + 1 < b1) a1 += (double)hv.y * (double)bin_center(b + 1);
                if (b + 2 < b1) a2 += (double)hv.z * (double)bin_center(b + 2);
                if (b + 3 < b1) a3 += (double)hv.w * (double)bin_center(b + 3);
            }
            double acc = (a0 + a1) + (a2 + a3);
            #pragma unroll
            for (int o = 16; o; o >>= 1) acc += __shfl_down_sync(0xffffffffu, acc, o);
            if (lane == 0) {
                unsigned part_unsel = __ldg(&h[b1]) - (keff - cab);
                acc += (double)part_unsel * (double)bin_center(b1);
                negr = bsa - acc - 0.5 * (double)keff;
            }
        }
        if (lane == 0) { sh_negr = negr; sh_kd = (double)k; sh_fb = (bcr < k); }
    }
    __syncthreads();

    // rare fallback: block-wide (top k-bc among below-cut negs)
    if (sh_fb) {
        for (int i = tid; i < NBINS; i += TPE) { f_h[i] = 0u; f_f[i] = 0.f; }
        __syncthreads();
        const size_t rb = (size_t)r * N;
        for (int i = tid; i < N; i += TPE) {
            float p = yp[rb + i], t = yt[rb + i];
            if (t == 0.f) {
                float a = fabsf(p);
                if (a < CUTF) {
                    unsigned bin = __float_as_uint(a) >> 21;
                    bin = min(bin, (unsigned)(NBINS - 1));
                    atomicAdd(&f_h[bin], 1u);
                    atomicAdd(&f_f[bin], fsl1(a));
                }
            }
        }
        __syncthreads();
        unsigned tc = 0;
        for (int i = tid; i < NBINS; i += TPE) tc += f_h[i];
        #pragma unroll
        for (int o = 16; o; o >>= 1) tc += __shfl_down_sync(0xffffffffu, tc, o);
        __shared__ unsigned s_tc[4];
        if (lane == 0) s_tc[w] = tc;
        __syncthreads();
        unsigned tot = s_tc[0] + s_tc[1] + s_tc[2] + s_tc[3];
        unsigned kc = k - bcr; if (kc > tot) kc = tot;
        if (kc > 0) {
            if (w == 0) {
                int b1; unsigned cab;
                warp_select_sh(f_h, kc, b1, cab);
                if (lane == 0) { s_b = b1; s_c = cab; }
            }
            __syncthreads();
            const int b1 = s_b; const unsigned cab = s_c;
            double ext = 0.0;
            for (int b = b1 + 1 + tid; b < NBINS; b += TPE) ext += (double)f_f[b];
            #pragma unroll
            for (int o = 16; o; o >>= 1) ext += __shfl_down_sync(0xffffffffu, ext, o);
            __shared__ double s_ext[4];
            if (lane == 0) s_ext[w] = ext;
            __syncthreads();
            if (tid == 0) {
                double e = s_ext[0] + s_ext[1] + s_ext[2] + s_ext[3];
                unsigned part = kc - cab;
                if (f_h[b1]) e += (double)part * ((double)f_f[b1] / (double)f_h[b1]);
                sh_negr += e;
            }
            __syncthreads();
        }
    }

    if (tid == 0) {
        atomicAdd(&g_z.ns, sh_negr);
        atomicAdd(&g_z.nc, sh_kd);
        __threadfence();
        sh_last = (atomicAdd(&g_z.ticket, 1u) == (unsigned)(B - 1)) ? 1 : 0;
    }
    __syncthreads();
    if (!sh_last) return;

    // ---- final scalar: single warp, 2 rows/lane, shfl double reduce ----
    if (w == 0) {
        __threadfence();
        double ps  = g_z.pos_sum[lane] + g_z.pos_sum[lane + 32];
        double pcs = (double)g_z.pos_cnt[lane] + (double)g_z.pos_cnt[lane + 32];
        #pragma unroll
        for (int o = 16; o; o >>= 1) {
            ps  += __shfl_down_sync(0xffffffffu, ps, o);
            pcs += __shfl_down_sync(0xffffffffu, pcs, o);
        }
        if (lane == 0) {
            double NS = g_z.ns, NC = g_z.nc;
            double pos_loss = (pcs > 0.0) ? ps / pcs : 0.0;
            double neg_loss = (NC > 0.0) ? NS / NC : 0.0;
            out[0] = (float)(2.0 * pos_loss + neg_loss);
        }
    }
}

// ---------------- launch ------------------------------------------------------
extern "C" void kernel_launch(void* const* d_in, const int* in_sizes, int n_in,
                              void* d_out, int out_size) {
    const float* yp = (const float*)d_in[0];
    const float* yt = (const float*)d_in[1];
    float* out = (float*)d_out;

    void* zp = nullptr;
    cudaGetSymbolAddress(&zp, g_z);
    cudaMemsetAsync(zp, 0, sizeof(Zeroed));

    pass_a<<<dim3(BPR, B), TPB>>>(yp, yt);
    pass_e<<<B, TPE>>>(yp, yt, out);
}